// round 4
// baseline (speedup 1.0000x reference)
#include <cuda_runtime.h>
#include <cstdint>

// Problem constants
#define NSAMPLES   524288
#define NFEAT      64
#define NGATES     64
#define NOUT       8
#define BASEN      66            // NFEAT + 2 (const-0 and const-1 entries)
#define MAXCONN    130           // BASEN + NGATES
#define BLK        128
#define STRIDE     129           // BLK + 1 (conflict-free transpose store)
#define SMEM_BYTES (MAXCONN * STRIDE * 4)

// All per-launch parameters in ONE constant block (single memcpy node).
// off first (512B), then w: rows are 32B-aligned -> float4 loads legal.
struct Params {
    uint2 off[NGATES];               // byte offsets of (a, b) operands
    float w[NGATES][NOUT];           // output_weights * output_scale (pre-folded)
};
__device__   Params g_stage;
__constant__ Params c_p;

// ---------------------------------------------------------------------------
// Prep: top-2 of gate_weights[i, 0 : 66+i]. Softmax is monotonic, so top-2 of
// probs == top-2 of raw logits. 16 threads per gate, shfl top-2 merge
// reduction; lexicographic (value, index) compare reproduces top_k
// lower-index-wins tie-breaking. Also folds output_scale into the weights.
// ---------------------------------------------------------------------------
__global__ void __launch_bounds__(1024)
prep_kernel(const float* __restrict__ gw,
            const float* __restrict__ ow,
            const float* __restrict__ sc) {
    const int tid  = threadIdx.x;
    const int gate = tid >> 4;        // 64 gates
    const int lane = tid & 15;        // 16 threads per gate
    const float* row = gw + gate * MAXCONN;
    const int n = BASEN + gate;

    float v1 = -3.4e38f, v2 = -3.4e38f;
    int   i1 = 0x7fffffff, i2 = 0x7fffffff;
#pragma unroll
    for (int k = 0; k < (MAXCONN + 15) / 16; ++k) {
        int j = lane + k * 16;
        if (j < n) {
            float v = row[j];
            if (v > v1 || (v == v1 && j < i1)) { v2 = v1; i2 = i1; v1 = v; i1 = j; }
            else if (v > v2 || (v == v2 && j < i2)) { v2 = v; i2 = j; }
        }
    }
#pragma unroll
    for (int d = 8; d >= 1; d >>= 1) {
        float ov1 = __shfl_down_sync(0xffffffffu, v1, d);
        int   oi1 = __shfl_down_sync(0xffffffffu, i1, d);
        float ov2 = __shfl_down_sync(0xffffffffu, v2, d);
        int   oi2 = __shfl_down_sync(0xffffffffu, i2, d);
        if (ov1 > v1 || (ov1 == v1 && oi1 < i1)) { v2 = v1; i2 = i1; v1 = ov1; i1 = oi1; }
        else if (ov1 > v2 || (ov1 == v2 && oi1 < i2)) { v2 = ov1; i2 = oi1; }
        if (ov2 > v1 || (ov2 == v1 && oi2 < i1)) { v2 = v1; i2 = i1; v1 = ov2; i1 = oi2; }
        else if (ov2 > v2 || (ov2 == v2 && oi2 < i2)) { v2 = ov2; i2 = oi2; }
    }
    if (lane == 0)
        g_stage.off[gate] = make_uint2((unsigned)(i1 * STRIDE * 4),
                                       (unsigned)(i2 * STRIDE * 4));
    if (tid < NGATES * NOUT) {
        int i = tid >> 3, j = tid & 7;
        g_stage.w[i][j] = ow[i * NOUT + j] * sc[j];
    }
}

// ---------------------------------------------------------------------------
// Main: one thread = one sample; per-sample buffer in smem [entry][sample].
// Prefetch distance 1, issued AFTER the STS of gate i: slots 0..i are all
// committed, so the prefetch can never be stale -> ZERO fixup instructions.
// The LDS(29cy)->use distance of one iteration is hidden by 3 warps/SMSP
// interleaving (~45 cycles between a warp's consecutive iterations).
// ptxas cannot prove the runtime-offset LDS disjoint from the STS, so it
// preserves the STS->LDS order -- conservatism gives us correctness for free.
// Weights read as 2x float4 (LDC.128) instead of 8 scalar constant reads.
// ---------------------------------------------------------------------------
__global__ void __launch_bounds__(BLK, 3)
circuit_kernel(const float* __restrict__ X, float* __restrict__ out) {
    extern __shared__ float sbuf[];
    const int tid = threadIdx.x;
    const long long base = (long long)blockIdx.x * BLK;

    // Load X tile transposed into smem via float4 streaming loads.
    // Element e = 4*(k*BLK+tid): sample s = e>>6, feature f = e&63;
    // bank (f*129+s)%32 = (f+s)%32 -> conflict-free STS.
    const float4* Xb = (const float4*)(X + base * NFEAT);
#pragma unroll
    for (int k = 0; k < NFEAT / 4; ++k) {
        float4 v = __ldcs(&Xb[k * BLK + tid]);
        int e = 4 * (k * BLK + tid);
        int s = e >> 6;
        int f = e & 63;
        sbuf[(f + 0) * STRIDE + s] = v.x;
        sbuf[(f + 1) * STRIDE + s] = v.y;
        sbuf[(f + 2) * STRIDE + s] = v.z;
        sbuf[(f + 3) * STRIDE + s] = v.w;
    }
    sbuf[64 * STRIDE + tid] = 0.0f;   // const 0
    sbuf[65 * STRIDE + tid] = 1.0f;   // const 1
    __syncthreads();

    char* col = (char*)(sbuf + tid);  // this sample's column (byte base)
    float acc[NOUT];
#pragma unroll
    for (int j = 0; j < NOUT; ++j) acc[j] = 0.0f;

    // Initial operands for gate 0 (always within the X/const region).
    uint2 o0 = c_p.off[0];
    float a = *(const float*)(col + o0.x);
    float b = *(const float*)(col + o0.y);

#pragma unroll
    for (int i = 0; i < NGATES; ++i) {
        float g = fmaf(-a, b, 1.0f);                  // g = 1 - a*b

        const unsigned Si = (unsigned)((BASEN + i) * STRIDE * 4);
        *(float*)(col + Si) = g;                      // STS, immediate offset

        if (i + 1 < NGATES) {                         // post-STS prefetch:
            uint2 o = c_p.off[i + 1];                 // slots 0..i committed,
            a = *(const float*)(col + o.x);           // never stale, no fixups
            b = *(const float*)(col + o.y);
        }

        float4 w0 = *(const float4*)&c_p.w[i][0];     // 2x LDC.128
        float4 w1 = *(const float4*)&c_p.w[i][4];
        acc[0] = fmaf(g, w0.x, acc[0]);
        acc[1] = fmaf(g, w0.y, acc[1]);
        acc[2] = fmaf(g, w0.z, acc[2]);
        acc[3] = fmaf(g, w0.w, acc[3]);
        acc[4] = fmaf(g, w1.x, acc[4]);
        acc[5] = fmaf(g, w1.y, acc[5]);
        acc[6] = fmaf(g, w1.z, acc[6]);
        acc[7] = fmaf(g, w1.w, acc[7]);
    }

    float4 r0 = make_float4(acc[0], acc[1], acc[2], acc[3]);
    float4 r1 = make_float4(acc[4], acc[5], acc[6], acc[7]);
    float4* op = (float4*)(out + (base + tid) * NOUT);
    __stcs(&op[0], r0);                               // streaming STG.128
    __stcs(&op[1], r1);
}

// ---------------------------------------------------------------------------
// Launch: prep -> ONE memcpy into the constant bank -> main kernel (3 nodes).
// ---------------------------------------------------------------------------
extern "C" void kernel_launch(void* const* d_in, const int* in_sizes, int n_in,
                              void* d_out, int out_size) {
    const float* X  = (const float*)d_in[0];  // (524288, 64)
    const float* gw = (const float*)d_in[1];  // (64, 130)
    const float* ow = (const float*)d_in[2];  // (64, 8)
    const float* sc = (const float*)d_in[3];  // (8,)
    float* out = (float*)d_out;               // (524288, 8)

    cudaFuncSetAttribute((const void*)circuit_kernel,
                         cudaFuncAttributeMaxDynamicSharedMemorySize, SMEM_BYTES);

    prep_kernel<<<1, 1024>>>(gw, ow, sc);

    void* gp = nullptr;
    cudaGetSymbolAddress(&gp, g_stage);
    cudaMemcpyToSymbolAsync(c_p, gp, sizeof(Params), 0,
                            cudaMemcpyDeviceToDevice, 0);

    circuit_kernel<<<NSAMPLES / BLK, BLK, SMEM_BYTES>>>(X, out);
}